// round 9
// baseline (speedup 1.0000x reference)
#include <cuda_runtime.h>
#include <math.h>

// N=500000, D=64, A=200000, temperature=1, cross_weight=1
#define NCE_BLOCKS 2048
#define WPB 8                    // warps per block (256 threads)
#define ROWS_PER_BLOCK 32        // streaming: 4 rows/warp, 2 row-pairs
#define ITEMS_PER_BLOCK (WPB * 8)  // NCE: 8 items per warp (4-lane groups)

__device__ float g_partials[NCE_BLOCKS];
__device__ unsigned int g_count = 0;

__device__ __forceinline__ float dot4(float4 a, float4 b) {
    return a.x * b.x + a.y * b.y + a.z * b.z + a.w * b.w;
}
__device__ __forceinline__ float4 avg4(float4 a, float4 b) {
    return make_float4(0.5f * (a.x + b.x), 0.5f * (a.y + b.y),
                       0.5f * (a.z + b.z), 0.5f * (a.w + b.w));
}
__device__ __forceinline__ float hsum16(float v) {
#pragma unroll
    for (int o = 8; o > 0; o >>= 1)
        v += __shfl_xor_sync(0xFFFFFFFFu, v, o);
    return v;
}
// two independent 16-lane reductions interleaved
__device__ __forceinline__ void hsum16x2(float& a, float& b) {
#pragma unroll
    for (int o = 8; o > 0; o >>= 1) {
        float ta = __shfl_xor_sync(0xFFFFFFFFu, a, o);
        float tb = __shfl_xor_sync(0xFFFFFFFFu, b, o);
        a += ta;
        b += tb;
    }
}
// 4-lane group reduction: 2 shuffle rounds, serves 8 groups per warp instruction
__device__ __forceinline__ float red4(float v) {
    v += __shfl_xor_sync(0xFFFFFFFFu, v, 2);
    v += __shfl_xor_sync(0xFFFFFFFFu, v, 1);
    return v;
}
__device__ __forceinline__ float warp_sum(float v) {
#pragma unroll
    for (int o = 16; o > 0; o >>= 1)
        v += __shfl_xor_sync(0xFFFFFFFFu, v, o);
    return v;
}
__device__ __forceinline__ float softplus_stable(float x) {
    return (x > 0.0f) ? (x + log1pf(expf(-x))) : log1pf(expf(x));
}
__device__ __forceinline__ float cos_sim(float dot, float n1sq, float n2sq) {
    float den = sqrtf(n1sq) * sqrtf(n2sq);
    return dot / fmaxf(den, 1e-8f);
}
__device__ __forceinline__ float4 ldcg4(const float* p) {
    return __ldcg((const float4*)p);
}

__global__ __launch_bounds__(256, 5) void mvr_fused_kernel(
    const float* __restrict__ g1, const float* __restrict__ g2,
    const float* __restrict__ s1, const float* __restrict__ s2,
    const float* __restrict__ w,
    const int* __restrict__ aidx, const int* __restrict__ nidx,
    float* __restrict__ out, int N, int A, int scalarOff)
{
    const int tid  = threadIdx.x;
    const int warp = tid >> 5;
    const int lane = tid & 31;

    if ((int)blockIdx.x >= NCE_BLOCKS) {
        // ---------- Streaming embedding fusion: 4 rows/warp (2 row-pairs) ----------
        const int half = lane >> 4;
        const int l16  = lane & 15;
        int row0 = ((int)blockIdx.x - NCE_BLOCKS) * ROWS_PER_BLOCK + warp * 2 + half;
        int row1 = row0 + 16;
        bool v0r = row0 < N;
        bool v1r = row1 < N;
        unsigned base0 = v0r ? ((unsigned)row0 * 64u + (unsigned)l16 * 4u) : 0u;
        unsigned base1 = v1r ? ((unsigned)row1 * 64u + (unsigned)l16 * 4u) : 0u;

        float4 a0 = __ldcs((const float4*)(g1 + base0));
        float4 b0 = __ldcs((const float4*)(g2 + base0));
        float4 c0 = __ldcs((const float4*)(s1 + base0));
        float4 d0 = __ldcs((const float4*)(s2 + base0));
        float4 a1 = __ldcs((const float4*)(g1 + base1));
        float4 b1 = __ldcs((const float4*)(g2 + base1));
        float4 c1 = __ldcs((const float4*)(s1 + base1));
        float4 d1 = __ldcs((const float4*)(s2 + base1));

        float4 wg = *(const float4*)(w + l16 * 4);
        float4 ws = *(const float4*)(w + 64 + l16 * 4);

        float4 ga0 = avg4(a0, b0);
        float4 sa0 = avg4(c0, d0);
        float4 ga1 = avg4(a1, b1);
        float4 sa1 = avg4(c1, d1);

        float p0 = dot4(ga0, wg) + dot4(sa0, ws);
        float p1 = dot4(ga1, wg) + dot4(sa1, ws);
        hsum16x2(p0, p1);

        float al0 = 1.0f / (1.0f + expf(-p0));
        float al1 = 1.0f / (1.0f + expf(-p1));

        float4 o0, o1;
        o0.x = fmaf(al0, ga0.x - sa0.x, sa0.x);
        o0.y = fmaf(al0, ga0.y - sa0.y, sa0.y);
        o0.z = fmaf(al0, ga0.z - sa0.z, sa0.z);
        o0.w = fmaf(al0, ga0.w - sa0.w, sa0.w);
        o1.x = fmaf(al1, ga1.x - sa1.x, sa1.x);
        o1.y = fmaf(al1, ga1.y - sa1.y, sa1.y);
        o1.z = fmaf(al1, ga1.z - sa1.z, sa1.z);
        o1.w = fmaf(al1, ga1.w - sa1.w, sa1.w);
        if (v0r) __stcs((float4*)(out + base0), o0);
        if (v1r) __stcs((float4*)(out + base1), o1);
        return;
    }

    // ---------- InfoNCE: 8 items per warp (4-lane groups), grid-stride ----------
    __shared__ float sh[WPB];
    __shared__ bool isLast;
    __shared__ float red[256];

    const int grp = lane >> 2;    // 0..7: item within warp
    const int sub = lane & 3;     // 0..3: 16-float segment of the row

    float acc = 0.0f;
    const int stride = NCE_BLOCKS * ITEMS_PER_BLOCK;
    int ibase0 = (int)blockIdx.x * ITEMS_PER_BLOCK + warp * 8;

#pragma unroll 1
    for (int ibase = ibase0; ibase < A; ibase += stride) {
        int item = ibase + grp;
        bool valid = item < A;
        int it = valid ? item : 0;
        int ai = __ldg(aidx + it);
        int ni = __ldg(nidx + it);
        unsigned ba = (unsigned)ai * 64u + (unsigned)sub * 4u;
        unsigned bn = (unsigned)ni * 64u + (unsigned)sub * 4u;

        float v0 = 0.f, v1 = 0.f, v2 = 0.f, v3 = 0.f, v4 = 0.f;
        float v5 = 0.f, v6 = 0.f, v7 = 0.f, v8 = 0.f, v9 = 0.f;
        float v10 = 0.f, v11 = 0.f, v12 = 0.f, v13 = 0.f, v14 = 0.f;

#pragma unroll 2
        for (int c = 0; c < 4; c++) {
            unsigned o = (unsigned)c * 16u;
            float4 g1a = ldcg4(g1 + ba + o);
            float4 g2a = ldcg4(g2 + ba + o);
            float4 g2n = ldcg4(g2 + bn + o);
            float4 s1a = ldcg4(s1 + ba + o);
            float4 s2a = ldcg4(s2 + ba + o);
            float4 s1n = ldcg4(s1 + bn + o);
            float4 s2n = ldcg4(s2 + bn + o);

            v0 += dot4(g1a, g2a);
            v1 += dot4(g1a, g1a);
            v2 += dot4(g2a, g2a);
            v3 += dot4(g1a, g2n);
            v4 += dot4(g2n, g2n);
            float4 gav = avg4(g1a, g2a);

            float4 snv = avg4(s1n, s2n);
            v5 += dot4(s1a, s2a);
            v6 += dot4(s1a, s1a);
            v7 += dot4(s2a, s2a);
            v8 += dot4(s1a, s2n);
            v9 += dot4(s2n, s2n);
            float4 sav = avg4(s1a, s2a);

            v10 += dot4(gav, sav);
            v11 += dot4(gav, gav);
            v12 += dot4(sav, sav);
            v13 += dot4(gav, snv);
            v14 += dot4(snv, snv);
        }

        // 4-lane reductions: 2 SHFL rounds each, 8 items per warp instruction
        v0 = red4(v0);   v1 = red4(v1);   v2 = red4(v2);
        v3 = red4(v3);   v4 = red4(v4);   v5 = red4(v5);
        v6 = red4(v6);   v7 = red4(v7);   v8 = red4(v8);
        v9 = red4(v9);   v10 = red4(v10); v11 = red4(v11);
        v12 = red4(v12); v13 = red4(v13); v14 = red4(v14);

        float loss = softplus_stable(cos_sim(v3,  v1,  v4)  - cos_sim(v0,  v1,  v2))
                   + softplus_stable(cos_sim(v8,  v6,  v9)  - cos_sim(v5,  v6,  v7))
                   + softplus_stable(cos_sim(v13, v11, v14) - cos_sim(v10, v11, v12));
        acc += valid ? loss : 0.0f;
    }

    // acc is replicated 4x within each group; sum and scale by 1/4 (exact)
    float tot = warp_sum(acc) * 0.25f;
    if (lane == 0) sh[warp] = tot;
    __syncthreads();

    if (tid == 0) {
        float s = 0.0f;
#pragma unroll
        for (int i = 0; i < WPB; i++) s += sh[i];
        g_partials[blockIdx.x] = s;
        __threadfence();
        unsigned t = atomicAdd(&g_count, 1u);
        isLast = (t == NCE_BLOCKS - 1);
    }
    __syncthreads();

    if (isLast) {
        __threadfence();
        float s = 0.0f;
        for (int i = tid; i < NCE_BLOCKS; i += 256)
            s += g_partials[i];
        red[tid] = s;
        __syncthreads();
#pragma unroll
        for (int st = 128; st > 0; st >>= 1) {
            if (tid < st) red[tid] += red[tid + st];
            __syncthreads();
        }
        if (tid == 0) {
            out[scalarOff] = red[0] / (float)A;
            g_count = 0;   // reset for next graph replay
        }
    }
}

extern "C" void kernel_launch(void* const* d_in, const int* in_sizes, int n_in,
                              void* d_out, int out_size)
{
    const float* g1 = (const float*)d_in[0];
    const float* g2 = (const float*)d_in[1];
    const float* s1 = (const float*)d_in[2];
    const float* s2 = (const float*)d_in[3];
    const float* w  = (const float*)d_in[4];
    const int* aidx = (const int*)d_in[5];
    const int* nidx = (const int*)d_in[6];
    float* out = (float*)d_out;

    int N = in_sizes[0] / 64;
    int A = in_sizes[5];

    int embBlocks = (N + ROWS_PER_BLOCK - 1) / ROWS_PER_BLOCK;  // 15625
    int scalarOff = N * 64;   // 32,000,000 fits in int

    mvr_fused_kernel<<<NCE_BLOCKS + embBlocks, 256>>>(
        g1, g2, s1, s2, w, aidx, nidx, out, N, A, scalarOff);
}

// round 10
// speedup vs baseline: 1.0948x; 1.0948x over previous
#include <cuda_runtime.h>
#include <math.h>

// N=500000, D=64, A=200000, temperature=1, cross_weight=1
#define NCE_BLOCKS 2048
#define WPB 8                    // warps per block (256 threads)
#define ROWS_PER_BLOCK 32        // streaming: 4 rows/warp, 2 row-pairs

__device__ float g_partials[NCE_BLOCKS];
__device__ unsigned int g_count = 0;

__device__ __forceinline__ float dot4(float4 a, float4 b) {
    return a.x * b.x + a.y * b.y + a.z * b.z + a.w * b.w;
}
__device__ __forceinline__ float4 avg4(float4 a, float4 b) {
    return make_float4(0.5f * (a.x + b.x), 0.5f * (a.y + b.y),
                       0.5f * (a.z + b.z), 0.5f * (a.w + b.w));
}
__device__ __forceinline__ float hsum16(float v) {
#pragma unroll
    for (int o = 8; o > 0; o >>= 1)
        v += __shfl_xor_sync(0xFFFFFFFFu, v, o);
    return v;
}
// two independent 16-lane reductions interleaved (hides shuffle latency)
__device__ __forceinline__ void hsum16x2(float& a, float& b) {
#pragma unroll
    for (int o = 8; o > 0; o >>= 1) {
        float ta = __shfl_xor_sync(0xFFFFFFFFu, a, o);
        float tb = __shfl_xor_sync(0xFFFFFFFFu, b, o);
        a += ta;
        b += tb;
    }
}
__device__ __forceinline__ float softplus_stable(float x) {
    return (x > 0.0f) ? (x + log1pf(expf(-x))) : log1pf(expf(x));
}
__device__ __forceinline__ float cos_sim(float dot, float n1sq, float n2sq) {
    float den = sqrtf(n1sq) * sqrtf(n2sq);
    return dot / fmaxf(den, 1e-8f);
}
__device__ __forceinline__ float4 ldcg4(const float* p) {
    return __ldcg((const float4*)p);
}
__device__ __forceinline__ void pf_l2(const float* p) {
    asm volatile("prefetch.global.L2 [%0];" :: "l"(p));
}

__global__ __launch_bounds__(256, 6) void mvr_fused_kernel(
    const float* __restrict__ g1, const float* __restrict__ g2,
    const float* __restrict__ s1, const float* __restrict__ s2,
    const float* __restrict__ w,
    const int* __restrict__ aidx, const int* __restrict__ nidx,
    float* __restrict__ out, int N, int A, int scalarOff)
{
    const int tid  = threadIdx.x;
    const int warp = tid >> 5;
    const int lane = tid & 31;
    const int half = lane >> 4;   // which 16-lane group
    const int l16  = lane & 15;   // lane within group (4 floats -> D=64)

    if ((int)blockIdx.x >= NCE_BLOCKS) {
        // ---------- Streaming embedding fusion: 4 rows/warp (2 row-pairs) ----------
        int row0 = ((int)blockIdx.x - NCE_BLOCKS) * ROWS_PER_BLOCK + warp * 2 + half;
        int row1 = row0 + 16;
        bool v0r = row0 < N;
        bool v1r = row1 < N;
        unsigned base0 = v0r ? ((unsigned)row0 * 64u + (unsigned)l16 * 4u) : 0u;
        unsigned base1 = v1r ? ((unsigned)row1 * 64u + (unsigned)l16 * 4u) : 0u;

        float4 a0 = __ldcs((const float4*)(g1 + base0));
        float4 b0 = __ldcs((const float4*)(g2 + base0));
        float4 c0 = __ldcs((const float4*)(s1 + base0));
        float4 d0 = __ldcs((const float4*)(s2 + base0));
        float4 a1 = __ldcs((const float4*)(g1 + base1));
        float4 b1 = __ldcs((const float4*)(g2 + base1));
        float4 c1 = __ldcs((const float4*)(s1 + base1));
        float4 d1 = __ldcs((const float4*)(s2 + base1));

        float4 wg = *(const float4*)(w + l16 * 4);
        float4 ws = *(const float4*)(w + 64 + l16 * 4);

        float4 ga0 = avg4(a0, b0);
        float4 sa0 = avg4(c0, d0);
        float4 ga1 = avg4(a1, b1);
        float4 sa1 = avg4(c1, d1);

        float p0 = dot4(ga0, wg) + dot4(sa0, ws);
        float p1 = dot4(ga1, wg) + dot4(sa1, ws);
        hsum16x2(p0, p1);   // interleaved chains

        float al0 = 1.0f / (1.0f + expf(-p0));
        float al1 = 1.0f / (1.0f + expf(-p1));

        float4 o0, o1;
        o0.x = fmaf(al0, ga0.x - sa0.x, sa0.x);
        o0.y = fmaf(al0, ga0.y - sa0.y, sa0.y);
        o0.z = fmaf(al0, ga0.z - sa0.z, sa0.z);
        o0.w = fmaf(al0, ga0.w - sa0.w, sa0.w);
        o1.x = fmaf(al1, ga1.x - sa1.x, sa1.x);
        o1.y = fmaf(al1, ga1.y - sa1.y, sa1.y);
        o1.z = fmaf(al1, ga1.z - sa1.z, sa1.z);
        o1.w = fmaf(al1, ga1.w - sa1.w, sa1.w);
        if (v0r) __stcs((float4*)(out + base0), o0);
        if (v1r) __stcs((float4*)(out + base1), o1);
        return;
    }

    // ---------- InfoNCE: 2 items per warp (16 lanes each), grid-stride ----------
    __shared__ float sh[WPB];
    __shared__ bool isLast;
    __shared__ float red[256];

    float acc = 0.0f;
    const int stride = NCE_BLOCKS * WPB * 2;
    int item0 = (int)blockIdx.x * (WPB * 2) + warp * 2 + half;

#pragma unroll 1
    for (int item = item0; item < A + half; item += stride) {
        bool valid = item < A;
        int it = valid ? item : 0;
        int ai = __ldg(aidx + it);
        int ni = __ldg(nidx + it);
        unsigned ba = (unsigned)ai * 64u + (unsigned)l16 * 4u;
        unsigned bn = (unsigned)ni * 64u + (unsigned)l16 * 4u;

        // all 7 row loads issued up front for MLP
        float4 g1a = ldcg4(g1 + ba);
        float4 g2a = ldcg4(g2 + ba);
        float4 g2n = ldcg4(g2 + bn);
        float4 s1a = ldcg4(s1 + ba);
        float4 s2a = ldcg4(s2 + ba);
        float4 s1n = ldcg4(s1 + bn);
        float4 s2n = ldcg4(s2 + bn);

        // L2-prefetch next iteration's rows (no registers held, fire-and-forget);
        // they land in L2 while this iteration's reduce/epilogue chain runs.
        {
            int nit = item + stride;
            if (nit < A + half) {
                int nc = (nit < A) ? nit : 0;
                int nai = __ldg(aidx + nc);
                int nni = __ldg(nidx + nc);
                unsigned pba = (unsigned)nai * 64u + (unsigned)l16 * 4u;
                unsigned pbn = (unsigned)nni * 64u + (unsigned)l16 * 4u;
                pf_l2(g1 + pba);
                pf_l2(g2 + pba);
                pf_l2(s1 + pba);
                pf_l2(s2 + pba);
                pf_l2(g2 + pbn);
                pf_l2(s1 + pbn);
                pf_l2(s2 + pbn);
            }
        }

        // graph view: consume g2n early
        float v0 = hsum16(dot4(g1a, g2a));
        float v1 = hsum16(dot4(g1a, g1a));
        float v2 = hsum16(dot4(g2a, g2a));
        float v3 = hsum16(dot4(g1a, g2n));
        float v4 = hsum16(dot4(g2n, g2n));       // g2n dead
        float4 gav = avg4(g1a, g2a);             // g1a,g2a -> gav

        // sequence view: consume s1n into snv immediately
        float4 snv = avg4(s1n, s2n);             // s1n dead
        float v5 = hsum16(dot4(s1a, s2a));
        float v6 = hsum16(dot4(s1a, s1a));
        float v7 = hsum16(dot4(s2a, s2a));
        float v8 = hsum16(dot4(s1a, s2n));
        float v9 = hsum16(dot4(s2n, s2n));       // s2n dead
        float4 sav = avg4(s1a, s2a);             // s1a,s2a -> sav

        // cross view
        float v10 = hsum16(dot4(gav, sav));
        float v11 = hsum16(dot4(gav, gav));
        float v12 = hsum16(dot4(sav, sav));
        float v13 = hsum16(dot4(gav, snv));
        float v14 = hsum16(dot4(snv, snv));

        float loss = softplus_stable(cos_sim(v3,  v1,  v4)  - cos_sim(v0,  v1,  v2))
                   + softplus_stable(cos_sim(v8,  v6,  v9)  - cos_sim(v5,  v6,  v7))
                   + softplus_stable(cos_sim(v13, v11, v14) - cos_sim(v10, v11, v12));
        acc += valid ? loss : 0.0f;
    }

    // combine the two half-warp accumulators
    float tot = acc + __shfl_xor_sync(0xFFFFFFFFu, acc, 16);
    if (lane == 0) sh[warp] = tot;
    __syncthreads();

    if (tid == 0) {
        float s = 0.0f;
#pragma unroll
        for (int i = 0; i < WPB; i++) s += sh[i];
        g_partials[blockIdx.x] = s;
        __threadfence();
        unsigned t = atomicAdd(&g_count, 1u);
        isLast = (t == NCE_BLOCKS - 1);
    }
    __syncthreads();

    if (isLast) {
        __threadfence();
        float s = 0.0f;
        for (int i = tid; i < NCE_BLOCKS; i += 256)
            s += g_partials[i];
        red[tid] = s;
        __syncthreads();
#pragma unroll
        for (int st = 128; st > 0; st >>= 1) {
            if (tid < st) red[tid] += red[tid + st];
            __syncthreads();
        }
        if (tid == 0) {
            out[scalarOff] = red[0] / (float)A;
            g_count = 0;   // reset for next graph replay
        }
    }
}

extern "C" void kernel_launch(void* const* d_in, const int* in_sizes, int n_in,
                              void* d_out, int out_size)
{
    const float* g1 = (const float*)d_in[0];
    const float* g2 = (const float*)d_in[1];
    const float* s1 = (const float*)d_in[2];
    const float* s2 = (const float*)d_in[3];
    const float* w  = (const float*)d_in[4];
    const int* aidx = (const int*)d_in[5];
    const int* nidx = (const int*)d_in[6];
    float* out = (float*)d_out;

    int N = in_sizes[0] / 64;
    int A = in_sizes[5];

    int embBlocks = (N + ROWS_PER_BLOCK - 1) / ROWS_PER_BLOCK;  // 15625
    int scalarOff = N * 64;   // 32,000,000 fits in int

    mvr_fused_kernel<<<NCE_BLOCKS + embBlocks, 256>>>(
        g1, g2, s1, s2, w, aidx, nidx, out, N, A, scalarOff);
}